// round 1
// baseline (speedup 1.0000x reference)
#include <cuda_runtime.h>
#include <math.h>

// Problem-fixed dims (from reference_code)
#define NN 100000
#define IN_X 32
#define IN_E 64
#define HID 128
#define OUT 64

// Scratch (static device globals — allocation-free). ~180 MB total.
__device__ __align__(16) float g_h0[NN * IN_E];
__device__ __align__(16) float g_ssum1[NN * IN_E];
__device__ __align__(16) float g_h1[NN * HID];
__device__ __align__(16) float g_ssum2[NN * HID];
__device__ __align__(16) float g_h2[NN * OUT];
__device__ __align__(16) float g_cnt[NN];

// ---------------------------------------------------------------------------
// Zero the accumulators (graph replay requires re-zeroing every launch).
// ---------------------------------------------------------------------------
__global__ void k_zero(int n_nodes) {
    int i = blockIdx.x * blockDim.x + threadIdx.x;
    int stride = gridDim.x * blockDim.x;
    int n1 = n_nodes * IN_E;
    int n2 = n_nodes * HID;
    for (int j = i; j < n1; j += stride) g_ssum1[j] = 0.0f;
    for (int j = i; j < n2; j += stride) g_ssum2[j] = 0.0f;
    for (int j = i; j < n_nodes; j += stride) g_cnt[j] = 0.0f;
}

// ---------------------------------------------------------------------------
// h0 = x @ W0 + b0      [N,32] @ [32,64]
// block: (64 cols, 4 rows). W0 staged in smem.
// ---------------------------------------------------------------------------
__global__ void k_lin0(const float* __restrict__ x,
                       const float* __restrict__ W0,
                       const float* __restrict__ b0, int N) {
    __shared__ float sW[IN_X * IN_E];   // 8 KB
    __shared__ float sx[4][IN_X];
    int tid = threadIdx.y * 64 + threadIdx.x;
    for (int i = tid; i < IN_X * IN_E; i += 256) sW[i] = W0[i];
    int row0 = blockIdx.x * 4;
    for (int i = tid; i < 4 * IN_X; i += 256) {
        int r = row0 + i / IN_X;
        sx[i / IN_X][i % IN_X] = (r < N) ? x[(size_t)r * IN_X + (i % IN_X)] : 0.0f;
    }
    __syncthreads();
    int j = threadIdx.x;
    int n = threadIdx.y;
    int row = row0 + n;
    if (row < N) {
        float acc = b0[j];
#pragma unroll
        for (int k = 0; k < IN_X; k++) acc += sx[n][k] * sW[k * IN_E + j];
        g_h0[(size_t)row * IN_E + j] = acc;
    }
}

// ---------------------------------------------------------------------------
// Scatter 1: ssum1[dst] += h0[src]; cnt[dst] += 1
// 16 threads per edge, one float4 each, vector red (sm_90+).
// ---------------------------------------------------------------------------
__device__ __forceinline__ void red_add_v4(float* p, float4 v) {
    asm volatile("red.global.add.v4.f32 [%0], {%1, %2, %3, %4};"
                 :: "l"(p), "f"(v.x), "f"(v.y), "f"(v.z), "f"(v.w)
                 : "memory");
}

__global__ void k_scatter1(const int* __restrict__ src,
                           const int* __restrict__ dst, int E) {
    int gid = blockIdx.x * blockDim.x + threadIdx.x;
    int e = gid >> 4;
    int c = gid & 15;
    if (e >= E) return;
    int s = src[e];
    int d = dst[e];
    float4 v = *reinterpret_cast<const float4*>(g_h0 + (size_t)s * IN_E + c * 4);
    red_add_v4(g_ssum1 + (size_t)d * IN_E + c * 4, v);
    if (c == 0) atomicAdd(g_cnt + d, 1.0f);
}

// ---------------------------------------------------------------------------
// SAGE1: h1 = relu( (ssum1/max(cnt,1)) @ W1l + b1l + h0 @ W1r )   [N,128]
// block: 128 threads (one output col each), 8 nodes register-blocked.
// ---------------------------------------------------------------------------
__global__ void k_sage1(const float* __restrict__ W1l,
                        const float* __restrict__ b1l,
                        const float* __restrict__ W1r, int N) {
    __shared__ float sa[8][IN_E];
    __shared__ float sh[8][IN_E];
    int tid = threadIdx.x;
    int n0 = blockIdx.x * 8;
    for (int i = tid; i < 8 * IN_E; i += 128) {
        int n = i / IN_E, k = i % IN_E;
        int row = n0 + n;
        if (row < N) {
            float inv = 1.0f / fmaxf(g_cnt[row], 1.0f);
            sa[n][k] = g_ssum1[(size_t)row * IN_E + k] * inv;
            sh[n][k] = g_h0[(size_t)row * IN_E + k];
        } else {
            sa[n][k] = 0.0f;
            sh[n][k] = 0.0f;
        }
    }
    __syncthreads();
    int j = tid;
    float acc[8];
    float bj = b1l[j];
#pragma unroll
    for (int n = 0; n < 8; n++) acc[n] = bj;
    for (int k = 0; k < IN_E; k++) {
        float wl = W1l[k * HID + j];
        float wr = W1r[k * HID + j];
#pragma unroll
        for (int n = 0; n < 8; n++) acc[n] += sa[n][k] * wl + sh[n][k] * wr;
    }
#pragma unroll
    for (int n = 0; n < 8; n++) {
        int row = n0 + n;
        if (row < N) g_h1[(size_t)row * HID + j] = fmaxf(acc[n], 0.0f);
    }
}

// ---------------------------------------------------------------------------
// Scatter 2: ssum2[dst] += h1[src]   (32 threads/edge, float4 each)
// ---------------------------------------------------------------------------
__global__ void k_scatter2(const int* __restrict__ src,
                           const int* __restrict__ dst, int E) {
    int gid = blockIdx.x * blockDim.x + threadIdx.x;
    int e = gid >> 5;
    int c = gid & 31;
    if (e >= E) return;
    int s = src[e];
    int d = dst[e];
    float4 v = *reinterpret_cast<const float4*>(g_h1 + (size_t)s * HID + c * 4);
    red_add_v4(g_ssum2 + (size_t)d * HID + c * 4, v);
}

// ---------------------------------------------------------------------------
// SAGE2: h2 = (ssum2/max(cnt,1)) @ W2l + b2l + h1 @ W2r   [N,64] (no relu)
// block: 64 threads, 8 nodes register-blocked, K=128.
// ---------------------------------------------------------------------------
__global__ void k_sage2(const float* __restrict__ W2l,
                        const float* __restrict__ b2l,
                        const float* __restrict__ W2r, int N) {
    __shared__ float sa[8][HID];
    __shared__ float sh[8][HID];
    int tid = threadIdx.x;
    int n0 = blockIdx.x * 8;
    for (int i = tid; i < 8 * HID; i += 64) {
        int n = i / HID, k = i % HID;
        int row = n0 + n;
        if (row < N) {
            float inv = 1.0f / fmaxf(g_cnt[row], 1.0f);
            sa[n][k] = g_ssum2[(size_t)row * HID + k] * inv;
            sh[n][k] = g_h1[(size_t)row * HID + k];
        } else {
            sa[n][k] = 0.0f;
            sh[n][k] = 0.0f;
        }
    }
    __syncthreads();
    int j = tid;
    float acc[8];
    float bj = b2l[j];
#pragma unroll
    for (int n = 0; n < 8; n++) acc[n] = bj;
    for (int k = 0; k < HID; k++) {
        float wl = W2l[k * OUT + j];
        float wr = W2r[k * OUT + j];
#pragma unroll
        for (int n = 0; n < 8; n++) acc[n] += sa[n][k] * wl + sh[n][k] * wr;
    }
#pragma unroll
    for (int n = 0; n < 8; n++) {
        int row = n0 + n;
        if (row < N) g_h2[(size_t)row * OUT + j] = acc[n];
    }
}

// ---------------------------------------------------------------------------
// Pred head: raw[e] = [h2[src], h2[dst]] . Wp + bp; out = {raw, sigmoid(raw)}
// One warp per edge.
// ---------------------------------------------------------------------------
__global__ void k_pred(const int* __restrict__ src,
                       const int* __restrict__ dst,
                       const float* __restrict__ Wp,
                       const float* __restrict__ bp,
                       float* __restrict__ out, int E) {
    int gid = blockIdx.x * blockDim.x + threadIdx.x;
    int e = gid >> 5;
    int lane = gid & 31;
    if (e >= E) return;
    int s = src[e];
    int d = dst[e];
    const float* hs = g_h2 + (size_t)s * OUT;
    const float* hd = g_h2 + (size_t)d * OUT;
    float acc = hs[lane]      * __ldg(Wp + lane)
              + hs[lane + 32] * __ldg(Wp + lane + 32)
              + hd[lane]      * __ldg(Wp + 64 + lane)
              + hd[lane + 32] * __ldg(Wp + 96 + lane);
#pragma unroll
    for (int o = 16; o > 0; o >>= 1) acc += __shfl_down_sync(0xffffffffu, acc, o);
    if (lane == 0) {
        float raw = acc + bp[0];
        out[e] = raw;
        out[(size_t)E + e] = 1.0f / (1.0f + expf(-raw));
    }
}

// ---------------------------------------------------------------------------
// Launch
// Inputs (metadata order):
//  0: x [N,32] f32        1: edge_index [2,E] i32
//  2: W0 [32,64]          3: b0 [64]
//  4: W1l [64,128]        5: b1l [128]       6: W1r [64,128]
//  7: W2l [128,64]        8: b2l [64]        9: W2r [128,64]
// 10: Wp [128,1]         11: bp [1]
// Output: raw [E] then sigmoid [E]  (2E f32)
// ---------------------------------------------------------------------------
extern "C" void kernel_launch(void* const* d_in, const int* in_sizes, int n_in,
                              void* d_out, int out_size) {
    const float* x   = (const float*)d_in[0];
    const int*   ei  = (const int*)d_in[1];
    const float* W0  = (const float*)d_in[2];
    const float* b0  = (const float*)d_in[3];
    const float* W1l = (const float*)d_in[4];
    const float* b1l = (const float*)d_in[5];
    const float* W1r = (const float*)d_in[6];
    const float* W2l = (const float*)d_in[7];
    const float* b2l = (const float*)d_in[8];
    const float* W2r = (const float*)d_in[9];
    const float* Wp  = (const float*)d_in[10];
    const float* bp  = (const float*)d_in[11];
    float* out = (float*)d_out;

    int N = in_sizes[0] / IN_X;     // 100000
    int E = in_sizes[1] / 2;        // 2000000
    const int* src = ei;
    const int* dst = ei + E;

    k_zero<<<4096, 256>>>(N);
    k_lin0<<<(N + 3) / 4, dim3(64, 4)>>>(x, W0, b0, N);

    {   // scatter1: 16 threads/edge
        long long t = (long long)E * 16;
        int blocks = (int)((t + 255) / 256);
        k_scatter1<<<blocks, 256>>>(src, dst, E);
    }
    k_sage1<<<(N + 7) / 8, 128>>>(W1l, b1l, W1r, N);

    {   // scatter2: 32 threads/edge
        long long t = (long long)E * 32;
        int blocks = (int)((t + 255) / 256);
        k_scatter2<<<blocks, 256>>>(src, dst, E);
    }
    k_sage2<<<(N + 7) / 8, 64>>>(W2l, b2l, W2r, N);

    {   // pred: one warp/edge
        long long t = (long long)E * 32;
        int blocks = (int)((t + 255) / 256);
        k_pred<<<blocks, 256>>>(src, dst, Wp, bp, out, E);
    }
}

// round 2
// speedup vs baseline: 1.4471x; 1.4471x over previous
#include <cuda_runtime.h>
#include <math.h>

// Problem-fixed dims
#define NN 100000
#define IN_X 32
#define IN_E 64
#define HID 128
#define OUT 64

// Scratch (static device globals — allocation-free). ~155 MB.
__device__ __align__(16) float g_h0[NN * IN_E];     // x@W0+b0
__device__ __align__(16) float g_ssum1[NN * IN_E];  // scatter of h0
__device__ __align__(16) float g_h1[NN * HID];      // SAGE1 out
__device__ __align__(16) float g_t2[NN * OUT];      // h1 @ W2l (pre-scatter transform)
__device__ __align__(16) float g_ssum2[NN * OUT];   // scatter of t2
__device__ __align__(16) float g_a[NN];             // h2 . Wp[0:64]
__device__ __align__(16) float g_b[NN];             // h2 . Wp[64:128]
__device__ __align__(16) float g_cnt[NN];

// ---------------------------------------------------------------------------
// Zero accumulators (required every graph replay).
// ---------------------------------------------------------------------------
__global__ void k_zero(int n_nodes) {
    int i = blockIdx.x * blockDim.x + threadIdx.x;
    int stride = gridDim.x * blockDim.x;
    int n1 = n_nodes * IN_E;   // ssum1
    int n2 = n_nodes * OUT;    // ssum2
    for (int j = i; j < n1; j += stride) g_ssum1[j] = 0.0f;
    for (int j = i; j < n2; j += stride) g_ssum2[j] = 0.0f;
    for (int j = i; j < n_nodes; j += stride) g_cnt[j] = 0.0f;
}

// ---------------------------------------------------------------------------
// h0 = x @ W0 + b0      [N,32] @ [32,64]
// ---------------------------------------------------------------------------
__global__ void k_lin0(const float* __restrict__ x,
                       const float* __restrict__ W0,
                       const float* __restrict__ b0, int N) {
    __shared__ float sW[IN_X * IN_E];   // 8 KB
    __shared__ float sx[4][IN_X];
    int tid = threadIdx.y * 64 + threadIdx.x;
    for (int i = tid; i < IN_X * IN_E; i += 256) sW[i] = W0[i];
    int row0 = blockIdx.x * 4;
    for (int i = tid; i < 4 * IN_X; i += 256) {
        int r = row0 + i / IN_X;
        sx[i / IN_X][i % IN_X] = (r < N) ? x[(size_t)r * IN_X + (i % IN_X)] : 0.0f;
    }
    __syncthreads();
    int j = threadIdx.x;
    int n = threadIdx.y;
    int row = row0 + n;
    if (row < N) {
        float acc = b0[j];
#pragma unroll
        for (int k = 0; k < IN_X; k++) acc += sx[n][k] * sW[k * IN_E + j];
        g_h0[(size_t)row * IN_E + j] = acc;
    }
}

// ---------------------------------------------------------------------------
// Vector no-return reduction (sm_90+)
// ---------------------------------------------------------------------------
__device__ __forceinline__ void red_add_v4(float* p, float4 v) {
    asm volatile("red.global.add.v4.f32 [%0], {%1, %2, %3, %4};"
                 :: "l"(p), "f"(v.x), "f"(v.y), "f"(v.z), "f"(v.w)
                 : "memory");
}

// ---------------------------------------------------------------------------
// Scatter 1: ssum1[dst] += h0[src]; cnt[dst] += 1.   16 threads/edge.
// ---------------------------------------------------------------------------
__global__ void k_scatter1(const int* __restrict__ src,
                           const int* __restrict__ dst, int E) {
    int gid = blockIdx.x * blockDim.x + threadIdx.x;
    int e = gid >> 4;
    int c = gid & 15;
    if (e >= E) return;
    int s = src[e];
    int d = dst[e];
    float4 v = *reinterpret_cast<const float4*>(g_h0 + (size_t)s * IN_E + c * 4);
    red_add_v4(g_ssum1 + (size_t)d * IN_E + c * 4, v);
    if (c == 0) atomicAdd(g_cnt + d, 1.0f);
}

// ---------------------------------------------------------------------------
// SAGE1 + fused t2:
//   h1 = relu( (ssum1/max(cnt,1)) @ W1l + b1l + h0 @ W1r )   [N,128]
//   t2 = h1 @ W2l                                            [N,64]
// 128 threads, 8 nodes/block, float4-vectorized k loop.
// ---------------------------------------------------------------------------
__global__ void k_sage1(const float* __restrict__ W1l,
                        const float* __restrict__ b1l,
                        const float* __restrict__ W1r,
                        const float* __restrict__ W2l, int N) {
    __shared__ float sa[8][IN_E];    // mean-aggregated input
    __shared__ float sh[8][IN_E];    // self input
    __shared__ float sh1[8][HID];    // h1 staging for fused t2
    int tid = threadIdx.x;
    int n0 = blockIdx.x * 8;

    for (int i = tid; i < 8 * IN_E; i += 128) {
        int n = i >> 6, k = i & 63;
        int row = n0 + n;
        if (row < N) {
            float inv = 1.0f / fmaxf(g_cnt[row], 1.0f);
            sa[n][k] = g_ssum1[(size_t)row * IN_E + k] * inv;
            sh[n][k] = g_h0[(size_t)row * IN_E + k];
        } else {
            sa[n][k] = 0.0f;
            sh[n][k] = 0.0f;
        }
    }
    __syncthreads();

    int j = tid;   // output column 0..127
    float acc[8];
    float bj = b1l[j];
#pragma unroll
    for (int n = 0; n < 8; n++) acc[n] = bj;

#pragma unroll
    for (int k = 0; k < IN_E; k += 4) {
        float wl0 = W1l[(k + 0) * HID + j];
        float wl1 = W1l[(k + 1) * HID + j];
        float wl2 = W1l[(k + 2) * HID + j];
        float wl3 = W1l[(k + 3) * HID + j];
        float wr0 = W1r[(k + 0) * HID + j];
        float wr1 = W1r[(k + 1) * HID + j];
        float wr2 = W1r[(k + 2) * HID + j];
        float wr3 = W1r[(k + 3) * HID + j];
#pragma unroll
        for (int n = 0; n < 8; n++) {
            float4 a4 = *reinterpret_cast<const float4*>(&sa[n][k]);
            float4 h4 = *reinterpret_cast<const float4*>(&sh[n][k]);
            acc[n] += a4.x * wl0 + a4.y * wl1 + a4.z * wl2 + a4.w * wl3
                    + h4.x * wr0 + h4.y * wr1 + h4.z * wr2 + h4.w * wr3;
        }
    }

#pragma unroll
    for (int n = 0; n < 8; n++) {
        float v = fmaxf(acc[n], 0.0f);
        sh1[n][j] = v;
        int row = n0 + n;
        if (row < N) g_h1[(size_t)row * HID + j] = v;
    }
    __syncthreads();

    // Fused t2 = h1 @ W2l. Thread -> (node n, 4 output cols j2..j2+3).
    int n  = tid >> 4;           // 0..7
    int j2 = (tid & 15) * 4;     // 0..60, 16B-aligned
    float t0 = 0.f, t1 = 0.f, t2 = 0.f, t3 = 0.f;
#pragma unroll
    for (int k = 0; k < HID; k += 4) {
        float4 h4 = *reinterpret_cast<const float4*>(&sh1[n][k]);
        float4 w0 = *reinterpret_cast<const float4*>(&W2l[(k + 0) * OUT + j2]);
        float4 w1 = *reinterpret_cast<const float4*>(&W2l[(k + 1) * OUT + j2]);
        float4 w2 = *reinterpret_cast<const float4*>(&W2l[(k + 2) * OUT + j2]);
        float4 w3 = *reinterpret_cast<const float4*>(&W2l[(k + 3) * OUT + j2]);
        t0 += h4.x * w0.x + h4.y * w1.x + h4.z * w2.x + h4.w * w3.x;
        t1 += h4.x * w0.y + h4.y * w1.y + h4.z * w2.y + h4.w * w3.y;
        t2 += h4.x * w0.z + h4.y * w1.z + h4.z * w2.z + h4.w * w3.z;
        t3 += h4.x * w0.w + h4.y * w1.w + h4.z * w2.w + h4.w * w3.w;
    }
    int row = n0 + n;
    if (row < N) {
        *reinterpret_cast<float4*>(&g_t2[(size_t)row * OUT + j2]) =
            make_float4(t0, t1, t2, t3);
    }
}

// ---------------------------------------------------------------------------
// Scatter 2: ssum2[dst] += t2[src]   (64-dim now; 16 threads/edge)
// ---------------------------------------------------------------------------
__global__ void k_scatter2(const int* __restrict__ src,
                           const int* __restrict__ dst, int E) {
    int gid = blockIdx.x * blockDim.x + threadIdx.x;
    int e = gid >> 4;
    int c = gid & 15;
    if (e >= E) return;
    int s = src[e];
    int d = dst[e];
    float4 v = *reinterpret_cast<const float4*>(g_t2 + (size_t)s * OUT + c * 4);
    red_add_v4(g_ssum2 + (size_t)d * OUT + c * 4, v);
}

// ---------------------------------------------------------------------------
// SAGE2 + fused pred precompute:
//   h2 = ssum2/max(cnt,1) + b2l + h1 @ W2r        [N,64]  (kept in registers)
//   a  = h2 . Wp[0:64],  b = h2 . Wp[64:128]      per node
// 64 threads (one col each), 8 nodes/block. h2 never written to global.
// ---------------------------------------------------------------------------
__global__ void k_sage2(const float* __restrict__ W2r,
                        const float* __restrict__ b2l,
                        const float* __restrict__ Wp, int N) {
    __shared__ float sh[8][HID];         // h1 rows
    __shared__ float redA[2][8];
    __shared__ float redB[2][8];
    int tid = threadIdx.x;               // 0..63
    int n0 = blockIdx.x * 8;

    for (int i = tid; i < 8 * HID; i += 64) {
        int n = i >> 7, k = i & 127;
        int row = n0 + n;
        sh[n][k] = (row < N) ? g_h1[(size_t)row * HID + k] : 0.0f;
    }

    int j = tid;
    float acc[8];
#pragma unroll
    for (int n = 0; n < 8; n++) {
        int row = n0 + n;
        acc[n] = b2l[j];
        if (row < N) {
            float inv = 1.0f / fmaxf(g_cnt[row], 1.0f);
            acc[n] += g_ssum2[(size_t)row * OUT + j] * inv;
        }
    }
    __syncthreads();

#pragma unroll
    for (int k = 0; k < HID; k += 4) {
        float w0 = W2r[(k + 0) * OUT + j];
        float w1 = W2r[(k + 1) * OUT + j];
        float w2 = W2r[(k + 2) * OUT + j];
        float w3 = W2r[(k + 3) * OUT + j];
#pragma unroll
        for (int n = 0; n < 8; n++) {
            float4 h4 = *reinterpret_cast<const float4*>(&sh[n][k]);
            acc[n] += h4.x * w0 + h4.y * w1 + h4.z * w2 + h4.w * w3;
        }
    }

    // per-node scalars a, b via warp-shuffle reduction over 64 cols (2 warps)
    float wpa = Wp[j];
    float wpb = Wp[OUT + j];
    int lane = tid & 31, warp = tid >> 5;
#pragma unroll
    for (int n = 0; n < 8; n++) {
        float pa = acc[n] * wpa;
        float pb = acc[n] * wpb;
#pragma unroll
        for (int o = 16; o > 0; o >>= 1) {
            pa += __shfl_down_sync(0xffffffffu, pa, o);
            pb += __shfl_down_sync(0xffffffffu, pb, o);
        }
        if (lane == 0) { redA[warp][n] = pa; redB[warp][n] = pb; }
    }
    __syncthreads();
    if (tid < 8) {
        int row = n0 + tid;
        if (row < N) {
            g_a[row] = redA[0][tid] + redA[1][tid];
            g_b[row] = redB[0][tid] + redB[1][tid];
        }
    }
}

// ---------------------------------------------------------------------------
// Pred head: raw[e] = a[src] + b[dst] + bp; out = {raw, sigmoid(raw)}
// One thread per edge; a/b tables are L2-resident (800 KB).
// ---------------------------------------------------------------------------
__global__ void k_pred(const int* __restrict__ src,
                       const int* __restrict__ dst,
                       const float* __restrict__ bp,
                       float* __restrict__ out, int E) {
    int e = blockIdx.x * blockDim.x + threadIdx.x;
    if (e >= E) return;
    float raw = g_a[src[e]] + g_b[dst[e]] + bp[0];
    out[e] = raw;
    out[(size_t)E + e] = 1.0f / (1.0f + expf(-raw));
}

// ---------------------------------------------------------------------------
// Launch
// ---------------------------------------------------------------------------
extern "C" void kernel_launch(void* const* d_in, const int* in_sizes, int n_in,
                              void* d_out, int out_size) {
    const float* x   = (const float*)d_in[0];
    const int*   ei  = (const int*)d_in[1];
    const float* W0  = (const float*)d_in[2];
    const float* b0  = (const float*)d_in[3];
    const float* W1l = (const float*)d_in[4];
    const float* b1l = (const float*)d_in[5];
    const float* W1r = (const float*)d_in[6];
    const float* W2l = (const float*)d_in[7];
    const float* b2l = (const float*)d_in[8];
    const float* W2r = (const float*)d_in[9];
    const float* Wp  = (const float*)d_in[10];
    const float* bp  = (const float*)d_in[11];
    float* out = (float*)d_out;

    int N = in_sizes[0] / IN_X;     // 100000
    int E = in_sizes[1] / 2;        // 2000000
    const int* src = ei;
    const int* dst = ei + E;

    k_zero<<<2048, 256>>>(N);
    k_lin0<<<(N + 3) / 4, dim3(64, 4)>>>(x, W0, b0, N);

    {   // scatter1: 16 threads/edge
        long long t = (long long)E * 16;
        int blocks = (int)((t + 255) / 256);
        k_scatter1<<<blocks, 256>>>(src, dst, E);
    }
    k_sage1<<<(N + 7) / 8, 128>>>(W1l, b1l, W1r, W2l, N);

    {   // scatter2: 16 threads/edge (64-dim t2)
        long long t = (long long)E * 16;
        int blocks = (int)((t + 255) / 256);
        k_scatter2<<<blocks, 256>>>(src, dst, E);
    }
    k_sage2<<<(N + 7) / 8, 64>>>(W2r, b2l, Wp, N);

    k_pred<<<(E + 255) / 256, 256>>>(src, dst, bp, out, E);
}

// round 3
// speedup vs baseline: 4.9022x; 3.3875x over previous
#include <cuda_runtime.h>
#include <math.h>

// Problem-fixed dims
#define NN 100000
#define IN_X 32
#define IN_E 64
#define HID 128
#define OUT 64

// ---- folded weights (computed by k_prep every launch; deterministic) ----
__device__ __align__(16) float g_W0l[IN_X * HID];  // W0 @ W1l
__device__ __align__(16) float g_W0r[IN_X * HID];  // W0 @ W1r
__device__ __align__(16) float g_c0l[HID];         // b0 @ W1l (gated by cnt>0)
__device__ __align__(16) float g_c1[HID];          // b1l + b0 @ W1r
__device__ __align__(16) float g_val[HID];         // W2l @ Wp[0:64]
__device__ __align__(16) float g_vbl[HID];         // W2l @ Wp[64:128]
__device__ __align__(16) float g_var[HID];         // W2r @ Wp[0:64]
__device__ __align__(16) float g_vbr[HID];         // W2r @ Wp[64:128]
__device__ float g_cab[2];                         // b2l . Wpa, b2l . Wpb

// ---- per-node scratch ----
__device__ __align__(16) float g_ssumx[NN * IN_X]; // scatter of raw x
__device__ __align__(16) float g_cnt[NN];
__device__ __align__(16) float g_pq[2 * NN];       // p,q  (h1 . val / vbl), scatter source
__device__ __align__(16) float g_r[2 * NN];        // ra,rb (h1 . var / vbr), self term
__device__ __align__(16) float g_spq[2 * NN];      // scattered sums of p,q
__device__ __align__(16) float g_ab[2 * NN];       // final per-node scalars

// ---------------------------------------------------------------------------
// Fold weights. 4 blocks x 128 threads; tiny.
// ---------------------------------------------------------------------------
__global__ void k_prep(const float* __restrict__ W0, const float* __restrict__ b0,
                       const float* __restrict__ W1l, const float* __restrict__ b1l,
                       const float* __restrict__ W1r,
                       const float* __restrict__ W2l, const float* __restrict__ b2l,
                       const float* __restrict__ W2r,
                       const float* __restrict__ Wp) {
    int j = threadIdx.x;   // 0..127
    int b = blockIdx.x;
    if (b == 0) {
        for (int k = 0; k < IN_X; k++) {
            float s = 0.f;
            for (int m = 0; m < IN_E; m++) s += W0[k * IN_E + m] * W1l[m * HID + j];
            g_W0l[k * HID + j] = s;
        }
        float s = 0.f;
        for (int m = 0; m < IN_E; m++) s += b0[m] * W1l[m * HID + j];
        g_c0l[j] = s;
    } else if (b == 1) {
        for (int k = 0; k < IN_X; k++) {
            float s = 0.f;
            for (int m = 0; m < IN_E; m++) s += W0[k * IN_E + m] * W1r[m * HID + j];
            g_W0r[k * HID + j] = s;
        }
        float s = 0.f;
        for (int m = 0; m < IN_E; m++) s += b0[m] * W1r[m * HID + j];
        g_c1[j] = b1l[j] + s;
    } else if (b == 2) {
        float sa = 0.f, sb = 0.f;
        for (int t = 0; t < OUT; t++) {
            float w = W2l[j * OUT + t];
            sa += w * Wp[t];
            sb += w * Wp[OUT + t];
        }
        g_val[j] = sa; g_vbl[j] = sb;
        if (j == 0) {
            float ca = 0.f, cb = 0.f;
            for (int t = 0; t < OUT; t++) { ca += b2l[t] * Wp[t]; cb += b2l[t] * Wp[OUT + t]; }
            g_cab[0] = ca; g_cab[1] = cb;
        }
    } else {
        float sa = 0.f, sb = 0.f;
        for (int t = 0; t < OUT; t++) {
            float w = W2r[j * OUT + t];
            sa += w * Wp[t];
            sb += w * Wp[OUT + t];
        }
        g_var[j] = sa; g_vbr[j] = sb;
    }
}

// ---------------------------------------------------------------------------
// Zero accumulators (ssumx 12.8MB + cnt + spq).
// ---------------------------------------------------------------------------
__global__ void k_zero(int N) {
    int i = blockIdx.x * blockDim.x + threadIdx.x;
    int stride = gridDim.x * blockDim.x;
    int n1 = (N * IN_X) / 4;
    float4 z = make_float4(0.f, 0.f, 0.f, 0.f);
    float4* p1 = reinterpret_cast<float4*>(g_ssumx);
    for (int k = i; k < n1; k += stride) p1[k] = z;
    for (int k = i; k < N; k += stride) g_cnt[k] = 0.f;
    float2* p2 = reinterpret_cast<float2*>(g_spq);
    float2 z2 = make_float2(0.f, 0.f);
    for (int k = i; k < N; k += stride) p2[k] = z2;
}

// ---------------------------------------------------------------------------
// Vector no-return reductions (sm_90+)
// ---------------------------------------------------------------------------
__device__ __forceinline__ void red_add_v4(float* p, float4 v) {
    asm volatile("red.global.add.v4.f32 [%0], {%1, %2, %3, %4};"
                 :: "l"(p), "f"(v.x), "f"(v.y), "f"(v.z), "f"(v.w) : "memory");
}
__device__ __forceinline__ void red_add_v2(float* p, float2 v) {
    asm volatile("red.global.add.v2.f32 [%0], {%1, %2};"
                 :: "l"(p), "f"(v.x), "f"(v.y) : "memory");
}

// ---------------------------------------------------------------------------
// Scatter 1: ssumx[dst] += x[src] (32-dim, 8 threads/edge), cnt[dst] += 1
// ---------------------------------------------------------------------------
__global__ void k_scatter1(const float* __restrict__ x,
                           const int* __restrict__ src,
                           const int* __restrict__ dst, int E) {
    int gid = blockIdx.x * blockDim.x + threadIdx.x;
    int e = gid >> 3;
    int c = gid & 7;
    if (e >= E) return;
    int s = src[e];
    int d = dst[e];
    float4 v = *reinterpret_cast<const float4*>(x + (size_t)s * IN_X + c * 4);
    red_add_v4(g_ssumx + (size_t)d * IN_X + c * 4, v);
    if (c == 0) atomicAdd(g_cnt + d, 1.0f);
}

// ---------------------------------------------------------------------------
// SAGE1 (folded) + layer-2 scalar projections:
//   h1 = relu( meanx @ W0l + flag*c0l + c1 + x @ W0r )        (in registers)
//   p = h1.val, q = h1.vbl  -> g_pq ;  ra = h1.var, rb = h1.vbr -> g_r
// 128 threads (one HID col each), 16 nodes register-blocked.
// ---------------------------------------------------------------------------
__global__ void __launch_bounds__(128) k_sage1(const float* __restrict__ x, int N) {
    __shared__ float smx[16][IN_X];
    __shared__ float ssx[16][IN_X];
    __shared__ float sflag[16];
    __shared__ float sred[16][4][4];   // [node][quantity][warp]
    int tid = threadIdx.x;
    int n0 = blockIdx.x * 16;

    {   // load 16 nodes x 32 cols of meanx and x (one float4 per thread)
        int n = tid >> 3;
        int k4 = (tid & 7) * 4;
        int row = n0 + n;
        float4 vm = make_float4(0.f, 0.f, 0.f, 0.f);
        float4 vs = vm;
        if (row < N) {
            float c = g_cnt[row];
            float inv = 1.0f / fmaxf(c, 1.0f);
            vm = *reinterpret_cast<const float4*>(g_ssumx + (size_t)row * IN_X + k4);
            vm.x *= inv; vm.y *= inv; vm.z *= inv; vm.w *= inv;
            vs = *reinterpret_cast<const float4*>(x + (size_t)row * IN_X + k4);
            if (k4 == 0) sflag[n] = (c > 0.f) ? 1.f : 0.f;
        } else if (k4 == 0) {
            sflag[n] = 0.f;
        }
        *reinterpret_cast<float4*>(&smx[n][k4]) = vm;
        *reinterpret_cast<float4*>(&ssx[n][k4]) = vs;
    }
    __syncthreads();

    int j = tid;
    float acc[16];
#pragma unroll
    for (int n = 0; n < 16; n++) acc[n] = 0.f;

#pragma unroll
    for (int k = 0; k < IN_X; k += 4) {
        float wl0 = g_W0l[(k + 0) * HID + j];
        float wl1 = g_W0l[(k + 1) * HID + j];
        float wl2 = g_W0l[(k + 2) * HID + j];
        float wl3 = g_W0l[(k + 3) * HID + j];
        float wr0 = g_W0r[(k + 0) * HID + j];
        float wr1 = g_W0r[(k + 1) * HID + j];
        float wr2 = g_W0r[(k + 2) * HID + j];
        float wr3 = g_W0r[(k + 3) * HID + j];
#pragma unroll
        for (int n = 0; n < 16; n++) {
            float4 a4 = *reinterpret_cast<const float4*>(&smx[n][k]);
            float4 h4 = *reinterpret_cast<const float4*>(&ssx[n][k]);
            acc[n] += a4.x * wl0 + a4.y * wl1 + a4.z * wl2 + a4.w * wl3
                    + h4.x * wr0 + h4.y * wr1 + h4.z * wr2 + h4.w * wr3;
        }
    }

    float c0lj = g_c0l[j], c1j = g_c1[j];
    float valj = g_val[j], vblj = g_vbl[j];
    float varj = g_var[j], vbrj = g_vbr[j];
    int lane = tid & 31, warp = tid >> 5;

#pragma unroll
    for (int n = 0; n < 16; n++) {
        float h1 = fmaxf(acc[n] + c1j + sflag[n] * c0lj, 0.f);
        float pa = h1 * valj;
        float pb = h1 * vblj;
        float ra = h1 * varj;
        float rb = h1 * vbrj;
#pragma unroll
        for (int o = 16; o > 0; o >>= 1) {
            pa += __shfl_down_sync(0xffffffffu, pa, o);
            pb += __shfl_down_sync(0xffffffffu, pb, o);
            ra += __shfl_down_sync(0xffffffffu, ra, o);
            rb += __shfl_down_sync(0xffffffffu, rb, o);
        }
        if (lane == 0) {
            sred[n][0][warp] = pa;
            sred[n][1][warp] = pb;
            sred[n][2][warp] = ra;
            sred[n][3][warp] = rb;
        }
    }
    __syncthreads();

    if (tid < 64) {
        int n = tid >> 2, q = tid & 3;
        float s = sred[n][q][0] + sred[n][q][1] + sred[n][q][2] + sred[n][q][3];
        int row = n0 + n;
        if (row < N) {
            if (q == 0)      g_pq[2 * (size_t)row]     = s;
            else if (q == 1) g_pq[2 * (size_t)row + 1] = s;
            else if (q == 2) g_r[2 * (size_t)row]      = s;
            else             g_r[2 * (size_t)row + 1]  = s;
        }
    }
}

// ---------------------------------------------------------------------------
// Scatter 2 (scalar): spq[dst] += pq[src]   — one thread/edge, 8B red.
// ---------------------------------------------------------------------------
__global__ void k_scatter2(const int* __restrict__ src,
                           const int* __restrict__ dst, int E) {
    int e = blockIdx.x * blockDim.x + threadIdx.x;
    if (e >= E) return;
    int s = src[e];
    int d = dst[e];
    float2 v = *reinterpret_cast<const float2*>(g_pq + 2 * (size_t)s);
    red_add_v2(g_spq + 2 * (size_t)d, v);
}

// ---------------------------------------------------------------------------
// Finish: a = spq.x/max(cnt,1) + ca + ra ;  b = spq.y/max(cnt,1) + cb + rb
// ---------------------------------------------------------------------------
__global__ void k_finish(int N) {
    int n = blockIdx.x * blockDim.x + threadIdx.x;
    if (n >= N) return;
    float inv = 1.0f / fmaxf(g_cnt[n], 1.0f);
    float2 spq = *reinterpret_cast<const float2*>(g_spq + 2 * (size_t)n);
    float2 r   = *reinterpret_cast<const float2*>(g_r   + 2 * (size_t)n);
    float2 ab;
    ab.x = spq.x * inv + g_cab[0] + r.x;
    ab.y = spq.y * inv + g_cab[1] + r.y;
    *reinterpret_cast<float2*>(g_ab + 2 * (size_t)n) = ab;
}

// ---------------------------------------------------------------------------
// Pred: raw[e] = a[src] + b[dst] + bp; out = {raw, sigmoid(raw)}
// ---------------------------------------------------------------------------
__global__ void k_pred(const int* __restrict__ src,
                       const int* __restrict__ dst,
                       const float* __restrict__ bp,
                       float* __restrict__ out, int E) {
    int e = blockIdx.x * blockDim.x + threadIdx.x;
    if (e >= E) return;
    float raw = g_ab[2 * (size_t)src[e]] + g_ab[2 * (size_t)dst[e] + 1] + bp[0];
    out[e] = raw;
    out[(size_t)E + e] = 1.0f / (1.0f + expf(-raw));
}

// ---------------------------------------------------------------------------
// Launch
// ---------------------------------------------------------------------------
extern "C" void kernel_launch(void* const* d_in, const int* in_sizes, int n_in,
                              void* d_out, int out_size) {
    const float* x   = (const float*)d_in[0];
    const int*   ei  = (const int*)d_in[1];
    const float* W0  = (const float*)d_in[2];
    const float* b0  = (const float*)d_in[3];
    const float* W1l = (const float*)d_in[4];
    const float* b1l = (const float*)d_in[5];
    const float* W1r = (const float*)d_in[6];
    const float* W2l = (const float*)d_in[7];
    const float* b2l = (const float*)d_in[8];
    const float* W2r = (const float*)d_in[9];
    const float* Wp  = (const float*)d_in[10];
    const float* bp  = (const float*)d_in[11];
    float* out = (float*)d_out;

    int N = in_sizes[0] / IN_X;   // 100000
    int E = in_sizes[1] / 2;      // 2000000
    const int* src = ei;
    const int* dst = ei + E;

    k_prep<<<4, 128>>>(W0, b0, W1l, b1l, W1r, W2l, b2l, W2r, Wp);
    k_zero<<<1024, 256>>>(N);

    {   // scatter1: 8 threads/edge
        long long t = (long long)E * 8;
        int blocks = (int)((t + 255) / 256);
        k_scatter1<<<blocks, 256>>>(x, src, dst, E);
    }
    k_sage1<<<(N + 15) / 16, 128>>>(x, N);
    k_scatter2<<<(E + 255) / 256, 256>>>(src, dst, E);
    k_finish<<<(N + 255) / 256, 256>>>(N);
    k_pred<<<(E + 255) / 256, 256>>>(src, dst, bp, out, E);
}

// round 4
// speedup vs baseline: 5.3123x; 1.0837x over previous
#include <cuda_runtime.h>
#include <math.h>

// Problem-fixed dims
#define NN 100000
#define IN_X 32
#define IN_E 64
#define HID 128
#define OUT 64

// ---- folded weights (computed by k_prep every launch; deterministic) ----
__device__ __align__(16) float g_W0l[IN_X * HID];  // W0 @ W1l
__device__ __align__(16) float g_W0r[IN_X * HID];  // W0 @ W1r
__device__ __align__(16) float g_c0l[HID];         // b0 @ W1l (gated by cnt>0)
__device__ __align__(16) float g_c1[HID];          // b1l + b0 @ W1r
__device__ __align__(16) float g_val[HID];         // W2l @ Wp[0:64]
__device__ __align__(16) float g_vbl[HID];         // W2l @ Wp[64:128]
__device__ __align__(16) float g_var[HID];         // W2r @ Wp[0:64]
__device__ __align__(16) float g_vbr[HID];         // W2r @ Wp[64:128]
__device__ float g_cab[2];                         // b2l . Wpa, b2l . Wpb

// ---- per-node scratch ----
__device__ __align__(16) float g_ssumx[NN * IN_X]; // scatter of raw x
__device__ __align__(16) float g_cnt[NN];
__device__ __align__(16) float g_pq[2 * NN];       // p,q  -> scatter source
__device__ __align__(16) float g_r[2 * NN];        // ra,rb (self term)
__device__ __align__(16) float g_spq[2 * NN];      // scattered sums of p,q
__device__ __align__(16) float g_ab[2 * NN];       // final per-node scalars

// ---------------------------------------------------------------------------
// Fold weights. 4 blocks x 128 threads; tiny.
// ---------------------------------------------------------------------------
__global__ void k_prep(const float* __restrict__ W0, const float* __restrict__ b0,
                       const float* __restrict__ W1l, const float* __restrict__ b1l,
                       const float* __restrict__ W1r,
                       const float* __restrict__ W2l, const float* __restrict__ b2l,
                       const float* __restrict__ W2r,
                       const float* __restrict__ Wp) {
    int j = threadIdx.x;   // 0..127
    int b = blockIdx.x;
    if (b == 0) {
        for (int k = 0; k < IN_X; k++) {
            float s = 0.f;
            for (int m = 0; m < IN_E; m++) s += W0[k * IN_E + m] * W1l[m * HID + j];
            g_W0l[k * HID + j] = s;
        }
        float s = 0.f;
        for (int m = 0; m < IN_E; m++) s += b0[m] * W1l[m * HID + j];
        g_c0l[j] = s;
    } else if (b == 1) {
        for (int k = 0; k < IN_X; k++) {
            float s = 0.f;
            for (int m = 0; m < IN_E; m++) s += W0[k * IN_E + m] * W1r[m * HID + j];
            g_W0r[k * HID + j] = s;
        }
        float s = 0.f;
        for (int m = 0; m < IN_E; m++) s += b0[m] * W1r[m * HID + j];
        g_c1[j] = b1l[j] + s;
    } else if (b == 2) {
        float sa = 0.f, sb = 0.f;
        for (int t = 0; t < OUT; t++) {
            float w = W2l[j * OUT + t];
            sa += w * Wp[t];
            sb += w * Wp[OUT + t];
        }
        g_val[j] = sa; g_vbl[j] = sb;
        if (j == 0) {
            float ca = 0.f, cb = 0.f;
            for (int t = 0; t < OUT; t++) { ca += b2l[t] * Wp[t]; cb += b2l[t] * Wp[OUT + t]; }
            g_cab[0] = ca; g_cab[1] = cb;
        }
    } else {
        float sa = 0.f, sb = 0.f;
        for (int t = 0; t < OUT; t++) {
            float w = W2r[j * OUT + t];
            sa += w * Wp[t];
            sb += w * Wp[OUT + t];
        }
        g_var[j] = sa; g_vbr[j] = sb;
    }
}

// ---------------------------------------------------------------------------
// Zero accumulators.
// ---------------------------------------------------------------------------
__global__ void k_zero(int N) {
    int i = blockIdx.x * blockDim.x + threadIdx.x;
    int stride = gridDim.x * blockDim.x;
    int n1 = (N * IN_X) / 4;
    float4 z = make_float4(0.f, 0.f, 0.f, 0.f);
    float4* p1 = reinterpret_cast<float4*>(g_ssumx);
    for (int k = i; k < n1; k += stride) p1[k] = z;
    for (int k = i; k < N; k += stride) g_cnt[k] = 0.f;
    float2* p2 = reinterpret_cast<float2*>(g_spq);
    float2 z2 = make_float2(0.f, 0.f);
    for (int k = i; k < N; k += stride) p2[k] = z2;
}

// ---------------------------------------------------------------------------
// Vector no-return reductions (sm_90+)
// ---------------------------------------------------------------------------
__device__ __forceinline__ void red_add_v4(float* p, float4 v) {
    asm volatile("red.global.add.v4.f32 [%0], {%1, %2, %3, %4};"
                 :: "l"(p), "f"(v.x), "f"(v.y), "f"(v.z), "f"(v.w) : "memory");
}
__device__ __forceinline__ void red_add_v2(float* p, float2 v) {
    asm volatile("red.global.add.v2.f32 [%0], {%1, %2};"
                 :: "l"(p), "f"(v.x), "f"(v.y) : "memory");
}

// ---------------------------------------------------------------------------
// Scatter 1: ssumx[dst] += x[src] (32-dim, 8 threads/edge), cnt[dst] += 1
// ---------------------------------------------------------------------------
__global__ void k_scatter1(const float* __restrict__ x,
                           const int* __restrict__ src,
                           const int* __restrict__ dst, int E) {
    int gid = blockIdx.x * blockDim.x + threadIdx.x;
    int e = gid >> 3;
    int c = gid & 7;
    if (e >= E) return;
    int s = src[e];
    int d = dst[e];
    float4 v = *reinterpret_cast<const float4*>(x + (size_t)s * IN_X + c * 4);
    red_add_v4(g_ssumx + (size_t)d * IN_X + c * 4, v);
    if (c == 0) atomicAdd(g_cnt + d, 1.0f);
}

// ---------------------------------------------------------------------------
// SAGE1 (folded), register/shuffle dataflow:
//   h1 = relu( meanx @ W0l + flag*c0l + c1 + x @ W0r )  (in registers)
//   p = h1.val, q = h1.vbl  -> g_pq ;  ra = h1.var, rb = h1.vbr -> g_r
// Block = 128 thr = 4 warps; each warp owns 8 nodes; lane holds node feature
// element [lane] in regs; each lane computes 4 output cols j4 = lane*4.
// Weights staged once per block in smem (32 KB), conflict-free LDS.128.
// ---------------------------------------------------------------------------
__global__ void __launch_bounds__(128) k_sage1(const float* __restrict__ x, int N) {
    __shared__ float4 sWl[IN_X][32];   // [k][j4]  16 KB
    __shared__ float4 sWr[IN_X][32];   // 16 KB
    int tid = threadIdx.x;
    int lane = tid & 31, wid = tid >> 5;

    {   // stage folded weights: 1024 float4 each
        const float4* Wl4 = reinterpret_cast<const float4*>(g_W0l);
        const float4* Wr4 = reinterpret_cast<const float4*>(g_W0r);
        for (int i = tid; i < IN_X * 32; i += 128) {
            sWl[i >> 5][i & 31] = Wl4[i];
            sWr[i >> 5][i & 31] = Wr4[i];
        }
    }

    int n0 = blockIdx.x * 32 + wid * 8;   // this warp's 8 nodes

    // lane<8 loads cnt for node n0+lane
    float cnt_l = 0.f;
    if (lane < 8 && n0 + lane < N) cnt_l = g_cnt[n0 + lane];
    float inv_l  = 1.0f / fmaxf(cnt_l, 1.0f);
    float flag_l = (cnt_l > 0.f) ? 1.0f : 0.0f;

    // node features in registers: lane holds element [lane] of each node
    float vm[8], vx[8];
#pragma unroll
    for (int n = 0; n < 8; n++) {
        int row = n0 + n;
        if (row < N) {
            vm[n] = g_ssumx[(size_t)row * IN_X + lane] *
                    __shfl_sync(0xffffffffu, inv_l, n);
            vx[n] = x[(size_t)row * IN_X + lane];
        } else {
            vm[n] = 0.f;
            vx[n] = 0.f;
        }
    }
    __syncthreads();

    float4 acc[8];
#pragma unroll
    for (int n = 0; n < 8; n++) acc[n] = make_float4(0.f, 0.f, 0.f, 0.f);

#pragma unroll 8
    for (int k = 0; k < IN_X; k++) {
        float4 wl = sWl[k][lane];
        float4 wr = sWr[k][lane];
#pragma unroll
        for (int n = 0; n < 8; n++) {
            float a = __shfl_sync(0xffffffffu, vm[n], k);
            float h = __shfl_sync(0xffffffffu, vx[n], k);
            acc[n].x += a * wl.x + h * wr.x;
            acc[n].y += a * wl.y + h * wr.y;
            acc[n].z += a * wl.z + h * wr.z;
            acc[n].w += a * wl.w + h * wr.w;
        }
    }

    // epilogue: bias + relu + 4 scalar projections per node, warp-reduced
    float4 c1v  = reinterpret_cast<const float4*>(g_c1)[lane];
    float4 c0v  = reinterpret_cast<const float4*>(g_c0l)[lane];
    float4 valv = reinterpret_cast<const float4*>(g_val)[lane];
    float4 vblv = reinterpret_cast<const float4*>(g_vbl)[lane];
    float4 varv = reinterpret_cast<const float4*>(g_var)[lane];
    float4 vbrv = reinterpret_cast<const float4*>(g_vbr)[lane];

#pragma unroll
    for (int n = 0; n < 8; n++) {
        float flag = __shfl_sync(0xffffffffu, flag_l, n);
        float hx = fmaxf(acc[n].x + c1v.x + flag * c0v.x, 0.f);
        float hy = fmaxf(acc[n].y + c1v.y + flag * c0v.y, 0.f);
        float hz = fmaxf(acc[n].z + c1v.z + flag * c0v.z, 0.f);
        float hw = fmaxf(acc[n].w + c1v.w + flag * c0v.w, 0.f);
        float pa = hx * valv.x + hy * valv.y + hz * valv.z + hw * valv.w;
        float pb = hx * vblv.x + hy * vblv.y + hz * vblv.z + hw * vblv.w;
        float ra = hx * varv.x + hy * varv.y + hz * varv.z + hw * varv.w;
        float rb = hx * vbrv.x + hy * vbrv.y + hz * vbrv.z + hw * vbrv.w;
#pragma unroll
        for (int o = 16; o > 0; o >>= 1) {
            pa += __shfl_down_sync(0xffffffffu, pa, o);
            pb += __shfl_down_sync(0xffffffffu, pb, o);
            ra += __shfl_down_sync(0xffffffffu, ra, o);
            rb += __shfl_down_sync(0xffffffffu, rb, o);
        }
        int row = n0 + n;
        if (lane == 0 && row < N) {
            *reinterpret_cast<float2*>(g_pq + 2 * (size_t)row) = make_float2(pa, pb);
            *reinterpret_cast<float2*>(g_r  + 2 * (size_t)row) = make_float2(ra, rb);
        }
    }
}

// ---------------------------------------------------------------------------
// Scatter 2 (scalar): spq[dst] += pq[src]   — one thread/edge, 8B red.
// ---------------------------------------------------------------------------
__global__ void k_scatter2(const int* __restrict__ src,
                           const int* __restrict__ dst, int E) {
    int e = blockIdx.x * blockDim.x + threadIdx.x;
    if (e >= E) return;
    int s = src[e];
    int d = dst[e];
    float2 v = *reinterpret_cast<const float2*>(g_pq + 2 * (size_t)s);
    red_add_v2(g_spq + 2 * (size_t)d, v);
}

// ---------------------------------------------------------------------------
// Finish: a = spq.x/max(cnt,1) + ca + ra ;  b = spq.y/max(cnt,1) + cb + rb
// ---------------------------------------------------------------------------
__global__ void k_finish(int N) {
    int n = blockIdx.x * blockDim.x + threadIdx.x;
    if (n >= N) return;
    float inv = 1.0f / fmaxf(g_cnt[n], 1.0f);
    float2 spq = *reinterpret_cast<const float2*>(g_spq + 2 * (size_t)n);
    float2 r   = *reinterpret_cast<const float2*>(g_r   + 2 * (size_t)n);
    float2 ab;
    ab.x = spq.x * inv + g_cab[0] + r.x;
    ab.y = spq.y * inv + g_cab[1] + r.y;
    *reinterpret_cast<float2*>(g_ab + 2 * (size_t)n) = ab;
}

// ---------------------------------------------------------------------------
// Pred: raw[e] = a[src] + b[dst] + bp; out = {raw, sigmoid(raw)}
// ---------------------------------------------------------------------------
__global__ void k_pred(const int* __restrict__ src,
                       const int* __restrict__ dst,
                       const float* __restrict__ bp,
                       float* __restrict__ out, int E) {
    int e = blockIdx.x * blockDim.x + threadIdx.x;
    if (e >= E) return;
    float raw = g_ab[2 * (size_t)src[e]] + g_ab[2 * (size_t)dst[e] + 1] + bp[0];
    out[e] = raw;
    out[(size_t)E + e] = 1.0f / (1.0f + expf(-raw));
}

// ---------------------------------------------------------------------------
// Launch
// ---------------------------------------------------------------------------
extern "C" void kernel_launch(void* const* d_in, const int* in_sizes, int n_in,
                              void* d_out, int out_size) {
    const float* x   = (const float*)d_in[0];
    const int*   ei  = (const int*)d_in[1];
    const float* W0  = (const float*)d_in[2];
    const float* b0  = (const float*)d_in[3];
    const float* W1l = (const float*)d_in[4];
    const float* b1l = (const float*)d_in[5];
    const float* W1r = (const float*)d_in[6];
    const float* W2l = (const float*)d_in[7];
    const float* b2l = (const float*)d_in[8];
    const float* W2r = (const float*)d_in[9];
    const float* Wp  = (const float*)d_in[10];
    const float* bp  = (const float*)d_in[11];
    float* out = (float*)d_out;

    int N = in_sizes[0] / IN_X;   // 100000
    int E = in_sizes[1] / 2;      // 2000000
    const int* src = ei;
    const int* dst = ei + E;

    k_prep<<<4, 128>>>(W0, b0, W1l, b1l, W1r, W2l, b2l, W2r, Wp);
    k_zero<<<1024, 256>>>(N);

    {   // scatter1: 8 threads/edge
        long long t = (long long)E * 8;
        int blocks = (int)((t + 255) / 256);
        k_scatter1<<<blocks, 256>>>(x, src, dst, E);
    }
    k_sage1<<<(N + 31) / 32, 128>>>(x, N);
    k_scatter2<<<(E + 255) / 256, 256>>>(src, dst, E);
    k_finish<<<(N + 255) / 256, 256>>>(N);
    k_pred<<<(E + 255) / 256, 256>>>(src, dst, bp, out, E);
}

// round 5
// speedup vs baseline: 5.9510x; 1.1202x over previous
#include <cuda_runtime.h>
#include <math.h>

// Problem-fixed dims
#define NN 100000
#define IN_X 32
#define IN_E 64
#define HID 128
#define OUT 64

// ---- folded weights (computed by k_prep every launch; deterministic) ----
__device__ __align__(16) float g_W0l[IN_X * HID];  // W0 @ W1l
__device__ __align__(16) float g_W0r[IN_X * HID];  // W0 @ W1r
__device__ __align__(16) float g_c0l[HID];         // b0 @ W1l (gated by cnt>0)
__device__ __align__(16) float g_c1[HID];          // b1l + b0 @ W1r
__device__ __align__(16) float g_val[HID];         // W2l @ Wp[0:64]
__device__ __align__(16) float g_vbl[HID];         // W2l @ Wp[64:128]
__device__ __align__(16) float g_var[HID];         // W2r @ Wp[0:64]
__device__ __align__(16) float g_vbr[HID];         // W2r @ Wp[64:128]
__device__ float g_cab[2];                         // b2l . Wpa, b2l . Wpb

// ---- per-node scratch ----
__device__ __align__(16) float g_ssumx[NN * IN_X]; // scatter of raw x
__device__ __align__(16) float g_cnt[NN];
__device__ __align__(16) float g_pq[2 * NN];       // p,q  -> scatter source
__device__ __align__(16) float g_r[2 * NN];        // ra,rb (self term)
__device__ __align__(16) float g_spq[2 * NN];      // scattered sums of p,q
__device__ __align__(16) float g_ab[2 * NN];       // final per-node scalars

// ---------------------------------------------------------------------------
// Fold weights. 4 blocks x 128 threads; tiny.
// ---------------------------------------------------------------------------
__global__ void k_prep(const float* __restrict__ W0, const float* __restrict__ b0,
                       const float* __restrict__ W1l, const float* __restrict__ b1l,
                       const float* __restrict__ W1r,
                       const float* __restrict__ W2l, const float* __restrict__ b2l,
                       const float* __restrict__ W2r,
                       const float* __restrict__ Wp) {
    int j = threadIdx.x;   // 0..127
    int b = blockIdx.x;
    if (b == 0) {
        for (int k = 0; k < IN_X; k++) {
            float s = 0.f;
            for (int m = 0; m < IN_E; m++) s += W0[k * IN_E + m] * W1l[m * HID + j];
            g_W0l[k * HID + j] = s;
        }
        float s = 0.f;
        for (int m = 0; m < IN_E; m++) s += b0[m] * W1l[m * HID + j];
        g_c0l[j] = s;
    } else if (b == 1) {
        for (int k = 0; k < IN_X; k++) {
            float s = 0.f;
            for (int m = 0; m < IN_E; m++) s += W0[k * IN_E + m] * W1r[m * HID + j];
            g_W0r[k * HID + j] = s;
        }
        float s = 0.f;
        for (int m = 0; m < IN_E; m++) s += b0[m] * W1r[m * HID + j];
        g_c1[j] = b1l[j] + s;
    } else if (b == 2) {
        float sa = 0.f, sb = 0.f;
        for (int t = 0; t < OUT; t++) {
            float w = W2l[j * OUT + t];
            sa += w * Wp[t];
            sb += w * Wp[OUT + t];
        }
        g_val[j] = sa; g_vbl[j] = sb;
        if (j == 0) {
            float ca = 0.f, cb = 0.f;
            for (int t = 0; t < OUT; t++) { ca += b2l[t] * Wp[t]; cb += b2l[t] * Wp[OUT + t]; }
            g_cab[0] = ca; g_cab[1] = cb;
        }
    } else {
        float sa = 0.f, sb = 0.f;
        for (int t = 0; t < OUT; t++) {
            float w = W2r[j * OUT + t];
            sa += w * Wp[t];
            sb += w * Wp[OUT + t];
        }
        g_var[j] = sa; g_vbr[j] = sb;
    }
}

// ---------------------------------------------------------------------------
// Zero accumulators.
// ---------------------------------------------------------------------------
__global__ void k_zero(int N) {
    int i = blockIdx.x * blockDim.x + threadIdx.x;
    int stride = gridDim.x * blockDim.x;
    int n1 = (N * IN_X) / 4;
    float4 z = make_float4(0.f, 0.f, 0.f, 0.f);
    float4* p1 = reinterpret_cast<float4*>(g_ssumx);
    for (int k = i; k < n1; k += stride) p1[k] = z;
    for (int k = i; k < N; k += stride) g_cnt[k] = 0.f;
    float2* p2 = reinterpret_cast<float2*>(g_spq);
    float2 z2 = make_float2(0.f, 0.f);
    for (int k = i; k < N; k += stride) p2[k] = z2;
}

// ---------------------------------------------------------------------------
// Vector no-return reductions (sm_90+)
// ---------------------------------------------------------------------------
__device__ __forceinline__ void red_add_v4(float* p, float4 v) {
    asm volatile("red.global.add.v4.f32 [%0], {%1, %2, %3, %4};"
                 :: "l"(p), "f"(v.x), "f"(v.y), "f"(v.z), "f"(v.w) : "memory");
}
__device__ __forceinline__ void red_add_v2(float* p, float2 v) {
    asm volatile("red.global.add.v2.f32 [%0], {%1, %2};"
                 :: "l"(p), "f"(v.x), "f"(v.y) : "memory");
}

// ---------------------------------------------------------------------------
// Scatter 1: ssumx[dst] += x[src] (32-dim, 8 threads/edge), cnt[dst] += 1
// ---------------------------------------------------------------------------
__global__ void k_scatter1(const float* __restrict__ x,
                           const int* __restrict__ src,
                           const int* __restrict__ dst, int E) {
    int gid = blockIdx.x * blockDim.x + threadIdx.x;
    int e = gid >> 3;
    int c = gid & 7;
    if (e >= E) return;
    int s = src[e];
    int d = dst[e];
    float4 v = *reinterpret_cast<const float4*>(x + (size_t)s * IN_X + c * 4);
    red_add_v4(g_ssumx + (size_t)d * IN_X + c * 4, v);
    if (c == 0) atomicAdd(g_cnt + d, 1.0f);
}

// ---------------------------------------------------------------------------
// SAGE1 (folded), shuffle-free inner loop:
//   h1 = relu( meanx @ W0l + flag*c0l + c1 + x @ W0r )   (in registers)
//   p=h1.val, q=h1.vbl -> g_pq ;  ra=h1.var, rb=h1.vbr -> g_r
// Block = 128 thr / 4 warps / 32 nodes. Warp owns 8 nodes; lane owns 4 cols.
// Weights (32 KB) + node features (8 KB) staged in smem. Inner loop:
// conflict-free LDS.128 weights + broadcast LDS.128 node rows -> ~13 FMA/LDS.
// ---------------------------------------------------------------------------
__global__ void __launch_bounds__(128) k_sage1(const float* __restrict__ x, int N) {
    __shared__ float4 sWl[IN_X][32];     // [k][lane] 16 KB
    __shared__ float4 sWr[IN_X][32];     // 16 KB
    __shared__ float smx[32][IN_X];      // mean-agg features, 4 KB
    __shared__ float ssx[32][IN_X];      // self features, 4 KB
    __shared__ float sinv[32];
    __shared__ float sflag[32];

    int tid = threadIdx.x;
    int lane = tid & 31, wid = tid >> 5;
    int n0 = blockIdx.x * 32;

    // stage folded weights (1024 float4 each)
    {
        const float4* Wl4 = reinterpret_cast<const float4*>(g_W0l);
        const float4* Wr4 = reinterpret_cast<const float4*>(g_W0r);
        for (int i = tid; i < IN_X * 32; i += 128) {
            sWl[i >> 5][i & 31] = Wl4[i];
            sWr[i >> 5][i & 31] = Wr4[i];
        }
    }
    // stage per-node cnt
    if (tid < 32) {
        float c = (n0 + tid < N) ? g_cnt[n0 + tid] : 0.f;
        sinv[tid]  = 1.0f / fmaxf(c, 1.0f);
        sflag[tid] = (c > 0.f) ? 1.0f : 0.0f;
    }
    __syncthreads();

    // stage node features: 32 nodes x 8 float4 per array
    for (int i = tid; i < 32 * 8; i += 128) {
        int n = i >> 3, k4 = (i & 7) * 4;
        int row = n0 + n;
        float4 vm = make_float4(0.f, 0.f, 0.f, 0.f);
        float4 vs = vm;
        if (row < N) {
            float inv = sinv[n];
            vm = *reinterpret_cast<const float4*>(g_ssumx + (size_t)row * IN_X + k4);
            vm.x *= inv; vm.y *= inv; vm.z *= inv; vm.w *= inv;
            vs = *reinterpret_cast<const float4*>(x + (size_t)row * IN_X + k4);
        }
        *reinterpret_cast<float4*>(&smx[n][k4]) = vm;
        *reinterpret_cast<float4*>(&ssx[n][k4]) = vs;
    }
    __syncthreads();

    int nb = wid * 8;   // this warp's first node (in-block)
    float4 acc[8];
#pragma unroll
    for (int n = 0; n < 8; n++) acc[n] = make_float4(0.f, 0.f, 0.f, 0.f);

#pragma unroll 2
    for (int k = 0; k < IN_X; k += 4) {
        float4 wl0 = sWl[k + 0][lane];
        float4 wl1 = sWl[k + 1][lane];
        float4 wl2 = sWl[k + 2][lane];
        float4 wl3 = sWl[k + 3][lane];
        float4 wr0 = sWr[k + 0][lane];
        float4 wr1 = sWr[k + 1][lane];
        float4 wr2 = sWr[k + 2][lane];
        float4 wr3 = sWr[k + 3][lane];
#pragma unroll
        for (int n = 0; n < 8; n++) {
            float4 a = *reinterpret_cast<const float4*>(&smx[nb + n][k]);   // broadcast
            float4 h = *reinterpret_cast<const float4*>(&ssx[nb + n][k]);   // broadcast
            acc[n].x += a.x * wl0.x + a.y * wl1.x + a.z * wl2.x + a.w * wl3.x
                      + h.x * wr0.x + h.y * wr1.x + h.z * wr2.x + h.w * wr3.x;
            acc[n].y += a.x * wl0.y + a.y * wl1.y + a.z * wl2.y + a.w * wl3.y
                      + h.x * wr0.y + h.y * wr1.y + h.z * wr2.y + h.w * wr3.y;
            acc[n].z += a.x * wl0.z + a.y * wl1.z + a.z * wl2.z + a.w * wl3.z
                      + h.x * wr0.z + h.y * wr1.z + h.z * wr2.z + h.w * wr3.z;
            acc[n].w += a.x * wl0.w + a.y * wl1.w + a.z * wl2.w + a.w * wl3.w
                      + h.x * wr0.w + h.y * wr1.w + h.z * wr2.w + h.w * wr3.w;
        }
    }

    // epilogue: bias + relu + 4 scalar projections per node, warp-reduced
    float4 c1v  = reinterpret_cast<const float4*>(g_c1)[lane];
    float4 c0v  = reinterpret_cast<const float4*>(g_c0l)[lane];
    float4 valv = reinterpret_cast<const float4*>(g_val)[lane];
    float4 vblv = reinterpret_cast<const float4*>(g_vbl)[lane];
    float4 varv = reinterpret_cast<const float4*>(g_var)[lane];
    float4 vbrv = reinterpret_cast<const float4*>(g_vbr)[lane];

#pragma unroll
    for (int n = 0; n < 8; n++) {
        float flag = sflag[nb + n];
        float hx = fmaxf(acc[n].x + c1v.x + flag * c0v.x, 0.f);
        float hy = fmaxf(acc[n].y + c1v.y + flag * c0v.y, 0.f);
        float hz = fmaxf(acc[n].z + c1v.z + flag * c0v.z, 0.f);
        float hw = fmaxf(acc[n].w + c1v.w + flag * c0v.w, 0.f);
        float pa = hx * valv.x + hy * valv.y + hz * valv.z + hw * valv.w;
        float pb = hx * vblv.x + hy * vblv.y + hz * vblv.z + hw * vblv.w;
        float ra = hx * varv.x + hy * varv.y + hz * varv.z + hw * varv.w;
        float rb = hx * vbrv.x + hy * vbrv.y + hz * vbrv.z + hw * vbrv.w;
#pragma unroll
        for (int o = 16; o > 0; o >>= 1) {
            pa += __shfl_down_sync(0xffffffffu, pa, o);
            pb += __shfl_down_sync(0xffffffffu, pb, o);
            ra += __shfl_down_sync(0xffffffffu, ra, o);
            rb += __shfl_down_sync(0xffffffffu, rb, o);
        }
        int row = n0 + nb + n;
        if (lane == 0 && row < N) {
            *reinterpret_cast<float2*>(g_pq + 2 * (size_t)row) = make_float2(pa, pb);
            *reinterpret_cast<float2*>(g_r  + 2 * (size_t)row) = make_float2(ra, rb);
        }
    }
}

// ---------------------------------------------------------------------------
// Scatter 2 (scalar): spq[dst] += pq[src]   — one thread/edge, 8B red.
// ---------------------------------------------------------------------------
__global__ void k_scatter2(const int* __restrict__ src,
                           const int* __restrict__ dst, int E) {
    int e = blockIdx.x * blockDim.x + threadIdx.x;
    if (e >= E) return;
    int s = src[e];
    int d = dst[e];
    float2 v = *reinterpret_cast<const float2*>(g_pq + 2 * (size_t)s);
    red_add_v2(g_spq + 2 * (size_t)d, v);
}

// ---------------------------------------------------------------------------
// Finish: a = spq.x/max(cnt,1) + ca + ra ;  b = spq.y/max(cnt,1) + cb + rb
// ---------------------------------------------------------------------------
__global__ void k_finish(int N) {
    int n = blockIdx.x * blockDim.x + threadIdx.x;
    if (n >= N) return;
    float inv = 1.0f / fmaxf(g_cnt[n], 1.0f);
    float2 spq = *reinterpret_cast<const float2*>(g_spq + 2 * (size_t)n);
    float2 r   = *reinterpret_cast<const float2*>(g_r   + 2 * (size_t)n);
    float2 ab;
    ab.x = spq.x * inv + g_cab[0] + r.x;
    ab.y = spq.y * inv + g_cab[1] + r.y;
    *reinterpret_cast<float2*>(g_ab + 2 * (size_t)n) = ab;
}

// ---------------------------------------------------------------------------
// Pred: raw[e] = a[src] + b[dst] + bp; out = {raw, sigmoid(raw)}
// ---------------------------------------------------------------------------
__global__ void k_pred(const int* __restrict__ src,
                       const int* __restrict__ dst,
                       const float* __restrict__ bp,
                       float* __restrict__ out, int E) {
    int e = blockIdx.x * blockDim.x + threadIdx.x;
    if (e >= E) return;
    float raw = g_ab[2 * (size_t)src[e]] + g_ab[2 * (size_t)dst[e] + 1] + bp[0];
    out[e] = raw;
    out[(size_t)E + e] = 1.0f / (1.0f + expf(-raw));
}

// ---------------------------------------------------------------------------
// Launch
// ---------------------------------------------------------------------------
extern "C" void kernel_launch(void* const* d_in, const int* in_sizes, int n_in,
                              void* d_out, int out_size) {
    const float* x   = (const float*)d_in[0];
    const int*   ei  = (const int*)d_in[1];
    const float* W0  = (const float*)d_in[2];
    const float* b0  = (const float*)d_in[3];
    const float* W1l = (const float*)d_in[4];
    const float* b1l = (const float*)d_in[5];
    const float* W1r = (const float*)d_in[6];
    const float* W2l = (const float*)d_in[7];
    const float* b2l = (const float*)d_in[8];
    const float* W2r = (const float*)d_in[9];
    const float* Wp  = (const float*)d_in[10];
    const float* bp  = (const float*)d_in[11];
    float* out = (float*)d_out;

    int N = in_sizes[0] / IN_X;   // 100000
    int E = in_sizes[1] / 2;      // 2000000
    const int* src = ei;
    const int* dst = ei + E;

    k_prep<<<4, 128>>>(W0, b0, W1l, b1l, W1r, W2l, b2l, W2r, Wp);
    k_zero<<<1024, 256>>>(N);

    {   // scatter1: 8 threads/edge
        long long t = (long long)E * 8;
        int blocks = (int)((t + 255) / 256);
        k_scatter1<<<blocks, 256>>>(x, src, dst, E);
    }
    k_sage1<<<(N + 31) / 32, 128>>>(x, N);
    k_scatter2<<<(E + 255) / 256, 256>>>(src, dst, E);
    k_finish<<<(N + 255) / 256, 256>>>(N);
    k_pred<<<(E + 255) / 256, 256>>>(src, dst, bp, out, E);
}